// round 7
// baseline (speedup 1.0000x reference)
#include <cuda_runtime.h>
#include <math.h>
#include <stdint.h>

#define Bc   2
#define Cc   64
#define Hc   192
#define Wc   192
#define Gc   4
#define Cgc  16
#define HW   (Hc*Wc)
#define Nsz  (Bc*HW)          // 73728 pixels total

#define X_ELEMS   ((size_t)Bc*Cc*HW)
#define VPAD 260              // s_val row pitch (floats), %4==0
typedef unsigned long long ull;

// Scratch (no allocations allowed)
__device__ float g_modulator[(size_t)Bc*36*HW];
__device__ float g_wt[4*9*16*64];               // [ (g*9+k)*16+c ][ o ]
__device__ float g_gsplit[(size_t)Bc*Gc*HW*16]; // [b*4+g][p][16ch]

// ---- helpers --------------------------------------------------------------
__device__ __forceinline__ ull ffma2(ull a, ull b, ull c) {
    ull d;
    asm("fma.rn.f32x2 %0, %1, %2, %3;" : "=l"(d) : "l"(a), "l"(b), "l"(c));
    return d;
}
__device__ __forceinline__ ull pack2(float lo, float hi) {
    ull r;
    asm("mov.b64 %0, {%1, %2};" : "=l"(r) : "f"(lo), "f"(hi));
    return r;
}
__device__ __forceinline__ float2 unpack2(ull v) {
    float2 f;
    asm("mov.b64 {%0, %1}, %2;" : "=f"(f.x), "=f"(f.y) : "l"(v));
    return f;
}
__device__ __forceinline__ float sigmoidf_(float v) {
    return 1.f / (1.f + expf(-v));
}
__device__ __forceinline__ void cp_async16(void* smem, const void* g) {
    uint32_t s = (uint32_t)__cvta_generic_to_shared(smem);
    asm volatile("cp.async.cg.shared.global [%0], [%1], 16;" :: "r"(s), "l"(g));
}

// ---------------------------------------------------------------------------
// Kernel 0a: weight transform  reg_w[o][ic][kh][kw] -> g_wt[(g*9+k)*16+c][o]
// ---------------------------------------------------------------------------
__global__ void wt_transform_kernel(const float* __restrict__ w, float* __restrict__ wt)
{
    int i = blockIdx.x * 256 + threadIdx.x;   // 36864 total
    int o = i & 63;
    int r = i >> 6;
    int c = r & 15;
    int r2 = r >> 4;
    int k = r2 % 9, g = r2 / 9;
    wt[i] = w[(o * 64 + g * 16 + c) * 9 + k];
}

// ---------------------------------------------------------------------------
// Kernel 0b: NCHW -> group-split transpose: [b][64][HW] -> [b*4+g][HW][16]
// ---------------------------------------------------------------------------
__global__ __launch_bounds__(256) void gsplit_kernel(
    const float* __restrict__ in, float* __restrict__ outp)
{
    __shared__ float t[32][33];
    const int tx = threadIdx.x & 31, ty = threadIdx.x >> 5;
    const int p0 = blockIdx.x * 32;
    const int c0 = blockIdx.y * 32;
    const int b  = blockIdx.z;
#pragma unroll
    for (int j = 0; j < 4; j++) {
        int c = c0 + ty + j * 8;
        t[ty + j * 8][tx] = in[((size_t)(b * Cc + c)) * HW + p0 + tx];
    }
    __syncthreads();
#pragma unroll
    for (int j = 0; j < 4; j++) {
        int p = p0 + ty + j * 8;
        int c = c0 + tx;
        int g = c >> 4, ci = c & 15;
        outp[((size_t)(b * 4 + g) * HW + p) * 16 + ci] = t[tx][ty + j * 8];
    }
}

// ---------------------------------------------------------------------------
// Conv bodies (shared-memory buffer passed in; 6336 floats)
// ---------------------------------------------------------------------------
__device__ __forceinline__ void offset_conv_body(
    float* sbuf,
    const float* __restrict__ wr, const float* __restrict__ src,
    const float* __restrict__ ow, const float* __restrict__ ob,
    float* __restrict__ out_off, int xb, int yb, int g, int b)
{
    float* s_in = sbuf;          // 4896
    float* s_w  = sbuf + 4896;   // 1440

    const int tid = threadIdx.x;
    const int tx = tid & 31, ty = tid >> 5;
    const int x0 = xb * 32, y0 = yb * 16;

    ull acc[2][9];
#pragma unroll
    for (int p = 0; p < 2; p++)
#pragma unroll
        for (int j = 0; j < 9; j++) acc[p][j] = 0ull;

#pragma unroll 1
    for (int chunk = 0; chunk < 4; chunk++) {
        const float* base = (chunk < 2 ? wr : src)
                          + ((size_t)(b * Cc + g * Cgc + (chunk & 1) * 8)) * HW;
        for (int i = tid; i < 4896; i += 256) {
            int c = i / 612, r = i % 612;
            int iy = r / 34, ix = r % 34;
            int gy = y0 - 1 + iy, gx = x0 - 1 + ix;
            float v = 0.f;
            if (gy >= 0 && gy < Hc && gx >= 0 && gx < Wc)
                v = base[(size_t)c * HW + gy * Wc + gx];
            s_in[i] = v;
        }
        for (int i = tid; i < 1440; i += 256) {
            int o = i % 20;
            int ck = i / 20;
            int k = ck % 9, c = ck / 9;
            s_w[i] = (o < 18) ? ow[(o * 32 + chunk * 8 + c) * 9 + k] : 0.f;
        }
        __syncthreads();

#pragma unroll 2
        for (int c = 0; c < 8; c++) {
#pragma unroll
            for (int t = 0; t < 9; t++) {
                const int kh = t / 3, kw = t % 3;
                const float* wrow = &s_w[(c * 9 + t) * 20];
                ulonglong2 l0 = *(const ulonglong2*)(wrow);
                ulonglong2 l1 = *(const ulonglong2*)(wrow + 4);
                ulonglong2 l2 = *(const ulonglong2*)(wrow + 8);
                ulonglong2 l3 = *(const ulonglong2*)(wrow + 12);
                ull w8 = *(const ull*)(wrow + 16);
#pragma unroll
                for (int p = 0; p < 2; p++) {
                    float v = s_in[c * 612 + (ty + p * 8 + kh) * 34 + tx + kw];
                    ull vv = pack2(v, v);
                    acc[p][0] = ffma2(vv, l0.x, acc[p][0]);
                    acc[p][1] = ffma2(vv, l0.y, acc[p][1]);
                    acc[p][2] = ffma2(vv, l1.x, acc[p][2]);
                    acc[p][3] = ffma2(vv, l1.y, acc[p][3]);
                    acc[p][4] = ffma2(vv, l2.x, acc[p][4]);
                    acc[p][5] = ffma2(vv, l2.y, acc[p][5]);
                    acc[p][6] = ffma2(vv, l3.x, acc[p][6]);
                    acc[p][7] = ffma2(vv, l3.y, acc[p][7]);
                    acc[p][8] = ffma2(vv, w8,  acc[p][8]);
                }
            }
        }
        __syncthreads();
    }

    const int x = x0 + tx;
#pragma unroll
    for (int p = 0; p < 2; p++) {
        int y = y0 + ty + p * 8;
#pragma unroll
        for (int j = 0; j < 9; j++) {
            float2 f = unpack2(acc[p][j]);
            int o0 = 2 * j, o1 = 2 * j + 1;
            float v0 = 100.f * sigmoidf_(f.x + ob[o0]) - 50.f;
            float v1 = 100.f * sigmoidf_(f.y + ob[o1]) - 50.f;
            out_off[((size_t)(b * 72 + g * 18 + o0) * Hc + y) * Wc + x] = v0;
            out_off[((size_t)(b * 72 + g * 18 + o1) * Hc + y) * Wc + x] = v1;
        }
    }
}

__device__ __forceinline__ void mod_conv_body(
    float* sbuf,
    const float* __restrict__ wr,
    const float* __restrict__ mw, const float* __restrict__ mb,
    float* __restrict__ modout, int xb, int yb, int b)
{
    float* s_in = sbuf;          // 2720
    float* s_w  = sbuf + 2720;   // 2880

    const int tid = threadIdx.x;
    const int tx = tid & 31;
    const int q = tid >> 5;
    const int ty = q & 3;
    const int oh = q >> 2;
    const int x0 = xb * 32, y0 = yb * 8;

    ull acc[2][9];
#pragma unroll
    for (int p = 0; p < 2; p++)
#pragma unroll
        for (int j = 0; j < 9; j++) acc[p][j] = 0ull;

#pragma unroll 1
    for (int chunk = 0; chunk < 8; chunk++) {
        const float* base = wr + ((size_t)(b * Cc + chunk * 8)) * HW;
        for (int i = tid; i < 2720; i += 256) {
            int c = i / 340, r = i % 340;
            int iy = r / 34, ix = r % 34;
            int gy = y0 - 1 + iy, gx = x0 - 1 + ix;
            float v = 0.f;
            if (gy >= 0 && gy < Hc && gx >= 0 && gx < Wc)
                v = base[(size_t)c * HW + gy * Wc + gx];
            s_in[i] = v;
        }
        for (int i = tid; i < 2880; i += 256) {
            int o = i % 20;
            int rr = i / 20;
            int h = rr & 1;
            int ck = rr >> 1;
            int k = ck % 9, c = ck / 9;
            s_w[i] = (o < 18) ? mw[((h * 18 + o) * 64 + chunk * 8 + c) * 9 + k] : 0.f;
        }
        __syncthreads();

#pragma unroll 2
        for (int c = 0; c < 8; c++) {
#pragma unroll
            for (int t = 0; t < 9; t++) {
                const int kh = t / 3, kw = t % 3;
                const float* wrow = &s_w[((c * 9 + t) * 2 + oh) * 20];
                ulonglong2 l0 = *(const ulonglong2*)(wrow);
                ulonglong2 l1 = *(const ulonglong2*)(wrow + 4);
                ulonglong2 l2 = *(const ulonglong2*)(wrow + 8);
                ulonglong2 l3 = *(const ulonglong2*)(wrow + 12);
                ull w8 = *(const ull*)(wrow + 16);
#pragma unroll
                for (int p = 0; p < 2; p++) {
                    float v = s_in[c * 340 + (ty + p * 4 + kh) * 34 + tx + kw];
                    ull vv = pack2(v, v);
                    acc[p][0] = ffma2(vv, l0.x, acc[p][0]);
                    acc[p][1] = ffma2(vv, l0.y, acc[p][1]);
                    acc[p][2] = ffma2(vv, l1.x, acc[p][2]);
                    acc[p][3] = ffma2(vv, l1.y, acc[p][3]);
                    acc[p][4] = ffma2(vv, l2.x, acc[p][4]);
                    acc[p][5] = ffma2(vv, l2.y, acc[p][5]);
                    acc[p][6] = ffma2(vv, l3.x, acc[p][6]);
                    acc[p][7] = ffma2(vv, l3.y, acc[p][7]);
                    acc[p][8] = ffma2(vv, w8,  acc[p][8]);
                }
            }
        }
        __syncthreads();
    }

    const int x = x0 + tx;
#pragma unroll
    for (int p = 0; p < 2; p++) {
        int y = y0 + ty + p * 4;
#pragma unroll
        for (int j = 0; j < 9; j++) {
            float2 f = unpack2(acc[p][j]);
            int o0 = oh * 18 + 2 * j, o1 = o0 + 1;
            float v0 = 2.f * sigmoidf_(f.x + mb[o0]);
            float v1 = 2.f * sigmoidf_(f.y + mb[o1]);
            modout[((size_t)(b * 36 + o0) * Hc + y) * Wc + x] = v0;
            modout[((size_t)(b * 36 + o1) * Hc + y) * Wc + x] = v1;
        }
    }
}

// ---------------------------------------------------------------------------
// Kernel 1+2 combined: 864 CTAs, interleaved 2:1 offset:mod so both types are
// co-resident per SM (each alone is latency-bound at ~45% fma utilization).
// ---------------------------------------------------------------------------
__global__ __launch_bounds__(256, 2) void uber_conv_kernel(
    const float* __restrict__ wr, const float* __restrict__ src,
    const float* __restrict__ ow, const float* __restrict__ ob,
    const float* __restrict__ mw, const float* __restrict__ mb,
    float* __restrict__ out_off, float* __restrict__ modout)
{
    __shared__ float sbuf[6336];
    const int i = blockIdx.x;           // 0..863
    const int r = i % 3;
    if (r < 2) {
        int idx = (i / 3) * 2 + r;      // 0..575
        int xb = idx % 6;
        int yb = (idx / 6) % 12;
        int zb = idx / 72;              // 0..7
        offset_conv_body(sbuf, wr, src, ow, ob, out_off, xb, yb, zb & 3, zb >> 2);
    } else {
        int idx = i / 3;                // 0..287
        int xb = idx % 6;
        int yb = (idx / 6) % 24;
        int b = idx / 144;
        mod_conv_body(sbuf, wr, mw, mb, modout, xb, yb, b);
    }
}

// ---------------------------------------------------------------------------
// Kernel 3: FUSED deform. Block = 256 px, 2 CTAs/SM. Cooperative gather
// (8 lanes/px, row-pair loads from group-split layout, shfl.xor x-combine),
// double-buffered SMEM tile, 8px x 8o FFMA2 GEMM per thread.
// ---------------------------------------------------------------------------
__global__ __launch_bounds__(256, 2) void deform_fused_kernel(
    const float* __restrict__ gsp,   // [b*4+g][HW][16]
    const float* __restrict__ off,   // [B,72,H,W]
    const float* __restrict__ mod,   // [B,36,H,W]
    const float* __restrict__ gwt,   // [36*16][64]
    float* __restrict__ out_x)
{
    __shared__ float s_val[2][16 * VPAD];
    __shared__ float s_wk[2][16 * 64];

    const int tid = threadIdx.x;
    const int warp = tid >> 5, lane = tid & 31;
    const int sub = lane >> 3;          // px within 4-px step
    const int jj = lane & 7;            // lane within px octet
    const int half = jj >> 2, qq = jj & 3;
    const int blk = blockIdx.x;
    const int b = blk / (HW / 256);
    const int ploc0 = (blk % (HW / 256)) * 256;

    const int tpx = tid & 31;
    const int to = tid >> 5;
    const float fhalf = (float)half;

    auto gather = [&](int i) {
        const int buf = i & 1;
        const int g = i / 9, k = i % 9;
        const int kh = k / 3, kw = k % 3;
        const float* gplane = gsp + (size_t)(b * 4 + g) * HW * 16;
        const float* offy = off + (size_t)(b * 72 + g * 18 + 2 * k) * HW + ploc0;
        const float* offx = offy + (size_t)HW;
        const float* modp = mod + (size_t)(b * 36 + g * 9 + k) * HW + ploc0;
        float* sv = s_val[buf];

#pragma unroll 4
        for (int s = 0; s < 8; s++) {
            const int pl = warp * 32 + s * 4 + sub;
            const int p = ploc0 + pl;
            const int yy = p / Wc, xx = p % Wc;
            float oy = __ldg(&offy[pl]);
            float ox = __ldg(&offx[pl]);
            float m  = __ldg(&modp[pl]);

            float py = oy + (float)(kh + yy - 1);
            float pxf = ox + (float)(kw + xx - 1);
            float fy = floorf(py), fx = floorf(pxf);
            float ly = py - fy, lx = pxf - fx;
            int y0 = (int)fy, x0 = (int)fx;

            float vx0 = (x0 >= 0 && x0 < Wc) ? 1.f : 0.f;
            float vx1 = (x0 >= -1 && x0 <= Wc - 2) ? 1.f : 0.f;
            float vy0 = (y0 >= 0 && y0 < Hc) ? 1.f : 0.f;
            float vy1 = (y0 >= -1 && y0 <= Hc - 2) ? 1.f : 0.f;

            int rbx = min(max(x0, 0), Wc - 2);
            int cx0 = min(max(x0, 0), Wc - 1);
            int cx1 = min(max(x0 + 1, 0), Wc - 1);
            float s0 = (float)(cx0 - rbx);
            float s1 = (float)(cx1 - rbx);
            float wx0 = (1.f - lx) * vx0;
            float wx1 = lx * vx1;
            float hw = wx0 * (s0 == fhalf ? 1.f : 0.f) + wx1 * (s1 == fhalf ? 1.f : 0.f);

            int ry0 = min(max(y0, 0), Hc - 1);
            int ry1 = min(max(y0 + 1, 0), Hc - 1);
            float a0 = (1.f - ly) * vy0 * m * hw;
            float a1 = ly * vy1 * m * hw;

            const float4* r0p = (const float4*)(gplane + ((size_t)(ry0 * Wc + rbx)) * 16) + jj;
            const float4* r1p = (const float4*)(gplane + ((size_t)(ry1 * Wc + rbx)) * 16) + jj;
            float4 v0 = __ldg(r0p);
            float4 v1 = __ldg(r1p);

            float4 u;
            u.x = v0.x * a0 + v1.x * a1;
            u.y = v0.y * a0 + v1.y * a1;
            u.z = v0.z * a0 + v1.z * a1;
            u.w = v0.w * a0 + v1.w * a1;
            u.x += __shfl_xor_sync(0xFFFFFFFFu, u.x, 4);
            u.y += __shfl_xor_sync(0xFFFFFFFFu, u.y, 4);
            u.z += __shfl_xor_sync(0xFFFFFFFFu, u.z, 4);
            u.w += __shfl_xor_sync(0xFFFFFFFFu, u.w, 4);

            if (half == 0) {
                int cb = qq * 4;
                sv[(cb + 0) * VPAD + pl] = u.x;
                sv[(cb + 1) * VPAD + pl] = u.y;
                sv[(cb + 2) * VPAD + pl] = u.z;
                sv[(cb + 3) * VPAD + pl] = u.w;
            }
        }
    };

    auto stage_w = [&](int i) {
        int flat = tid * 4;
        int c = flat >> 6, o = flat & 63;
        cp_async16(&s_wk[i & 1][c * 64 + o], &gwt[(i * 16 + c) * 64 + o]);
        asm volatile("cp.async.commit_group;" ::: "memory");
    };

    ull acc[8][4];
#pragma unroll
    for (int p = 0; p < 8; p++)
#pragma unroll
        for (int j = 0; j < 4; j++) acc[p][j] = 0ull;

    stage_w(0);
    gather(0);

#pragma unroll 1
    for (int i = 0; i < 36; i++) {
        asm volatile("cp.async.wait_group 0;" ::: "memory");
        __syncthreads();
        if (i < 35) { stage_w(i + 1); gather(i + 1); }

        const float* vb_ = s_val[i & 1];
        const float* wb_ = s_wk[i & 1];
#pragma unroll
        for (int c = 0; c < 16; c++) {
            float4 va  = *(const float4*)&vb_[c * VPAD + tpx * 4];
            float4 vbv = *(const float4*)&vb_[c * VPAD + 128 + tpx * 4];
            ulonglong2 wA = *(const ulonglong2*)&wb_[c * 64 + to * 4];
            ulonglong2 wB = *(const ulonglong2*)&wb_[c * 64 + 32 + to * 4];
            ull vv;
            vv = pack2(va.x, va.x);
            acc[0][0] = ffma2(vv, wA.x, acc[0][0]); acc[0][1] = ffma2(vv, wA.y, acc[0][1]);
            acc[0][2] = ffma2(vv, wB.x, acc[0][2]); acc[0][3] = ffma2(vv, wB.y, acc[0][3]);
            vv = pack2(va.y, va.y);
            acc[1][0] = ffma2(vv, wA.x, acc[1][0]); acc[1][1] = ffma2(vv, wA.y, acc[1][1]);
            acc[1][2] = ffma2(vv, wB.x, acc[1][2]); acc[1][3] = ffma2(vv, wB.y, acc[1][3]);
            vv = pack2(va.z, va.z);
            acc[2][0] = ffma2(vv, wA.x, acc[2][0]); acc[2][1] = ffma2(vv, wA.y, acc[2][1]);
            acc[2][2] = ffma2(vv, wB.x, acc[2][2]); acc[2][3] = ffma2(vv, wB.y, acc[2][3]);
            vv = pack2(va.w, va.w);
            acc[3][0] = ffma2(vv, wA.x, acc[3][0]); acc[3][1] = ffma2(vv, wA.y, acc[3][1]);
            acc[3][2] = ffma2(vv, wB.x, acc[3][2]); acc[3][3] = ffma2(vv, wB.y, acc[3][3]);
            vv = pack2(vbv.x, vbv.x);
            acc[4][0] = ffma2(vv, wA.x, acc[4][0]); acc[4][1] = ffma2(vv, wA.y, acc[4][1]);
            acc[4][2] = ffma2(vv, wB.x, acc[4][2]); acc[4][3] = ffma2(vv, wB.y, acc[4][3]);
            vv = pack2(vbv.y, vbv.y);
            acc[5][0] = ffma2(vv, wA.x, acc[5][0]); acc[5][1] = ffma2(vv, wA.y, acc[5][1]);
            acc[5][2] = ffma2(vv, wB.x, acc[5][2]); acc[5][3] = ffma2(vv, wB.y, acc[5][3]);
            vv = pack2(vbv.z, vbv.z);
            acc[6][0] = ffma2(vv, wA.x, acc[6][0]); acc[6][1] = ffma2(vv, wA.y, acc[6][1]);
            acc[6][2] = ffma2(vv, wB.x, acc[6][2]); acc[6][3] = ffma2(vv, wB.y, acc[6][3]);
            vv = pack2(vbv.w, vbv.w);
            acc[7][0] = ffma2(vv, wA.x, acc[7][0]); acc[7][1] = ffma2(vv, wA.y, acc[7][1]);
            acc[7][2] = ffma2(vv, wB.x, acc[7][2]); acc[7][3] = ffma2(vv, wB.y, acc[7][3]);
        }
    }

    // Epilogue
    const size_t pbase = (size_t)ploc0;
#pragma unroll
    for (int qj = 0; qj < 4; qj++) {
        int o = (qj < 2) ? (to * 4 + 2 * qj) : (32 + to * 4 + 2 * (qj - 2));
        float2 f0 = unpack2(acc[0][qj]);
        float2 f1 = unpack2(acc[1][qj]);
        float2 f2 = unpack2(acc[2][qj]);
        float2 f3 = unpack2(acc[3][qj]);
        float4 lo = make_float4(f0.x, f1.x, f2.x, f3.x);
        float4 hi = make_float4(f0.y, f1.y, f2.y, f3.y);
        *(float4*)&out_x[((size_t)(b * Cc + o)) * HW + pbase + tpx * 4] = lo;
        *(float4*)&out_x[((size_t)(b * Cc + o + 1)) * HW + pbase + tpx * 4] = hi;
        float2 g0 = unpack2(acc[4][qj]);
        float2 g1 = unpack2(acc[5][qj]);
        float2 g2 = unpack2(acc[6][qj]);
        float2 g3 = unpack2(acc[7][qj]);
        float4 lo2 = make_float4(g0.x, g1.x, g2.x, g3.x);
        float4 hi2 = make_float4(g0.y, g1.y, g2.y, g3.y);
        *(float4*)&out_x[((size_t)(b * Cc + o)) * HW + pbase + 128 + tpx * 4] = lo2;
        *(float4*)&out_x[((size_t)(b * Cc + o + 1)) * HW + pbase + 128 + tpx * 4] = hi2;
    }
}

// ---------------------------------------------------------------------------
extern "C" void kernel_launch(void* const* d_in, const int* in_sizes, int n_in,
                              void* d_out, int out_size)
{
    const float* warp_ref = (const float*)d_in[0];
    const float* source   = (const float*)d_in[1];
    const float* offset_w = (const float*)d_in[2];
    const float* offset_b = (const float*)d_in[3];
    const float* mod_w    = (const float*)d_in[4];
    const float* mod_b    = (const float*)d_in[5];
    const float* reg_w    = (const float*)d_in[6];

    float* out_x   = (float*)d_out;             // [B,64,H,W]
    float* out_off = (float*)d_out + X_ELEMS;   // [B,72,H,W]

    float *mod_scratch, *wt_scratch, *gsp_scratch;
    cudaGetSymbolAddress((void**)&mod_scratch, g_modulator);
    cudaGetSymbolAddress((void**)&wt_scratch, g_wt);
    cudaGetSymbolAddress((void**)&gsp_scratch, g_gsplit);

    dim3 blk(256);
    wt_transform_kernel<<<144, blk>>>(reg_w, wt_scratch);
    gsplit_kernel<<<dim3(HW / 32, 2, Bc), blk>>>(warp_ref, gsp_scratch);
    uber_conv_kernel<<<864, blk>>>(warp_ref, source, offset_w, offset_b,
                                   mod_w, mod_b, out_off, mod_scratch);
    deform_fused_kernel<<<dim3(Nsz / 256), blk>>>(gsp_scratch, out_off, mod_scratch, wt_scratch, out_x);
}

// round 8
// speedup vs baseline: 1.3092x; 1.3092x over previous
#include <cuda_runtime.h>
#include <math.h>
#include <stdint.h>

#define Bc   2
#define Cc   64
#define Hc   192
#define Wc   192
#define Gc   4
#define Cgc  16
#define HW   (Hc*Wc)
#define Nsz  (Bc*HW)          // 73728 pixels total

#define X_ELEMS   ((size_t)Bc*Cc*HW)
#define VPAD 264              // s_val row pitch: 264%32==8 -> conflict-free B frags
typedef unsigned long long ull;

// Scratch (no allocations allowed)
__device__ float g_modulator[(size_t)Bc*36*HW];
__device__ float g_wt[4*9*16*64];               // [ (g*9+k)*16+c ][ o ]  (tf32-rounded)
__device__ float g_gsplit[(size_t)Bc*Gc*HW*16]; // [b*4+g][p][16ch]

// ---- helpers --------------------------------------------------------------
__device__ __forceinline__ ull ffma2(ull a, ull b, ull c) {
    ull d;
    asm("fma.rn.f32x2 %0, %1, %2, %3;" : "=l"(d) : "l"(a), "l"(b), "l"(c));
    return d;
}
__device__ __forceinline__ ull pack2(float lo, float hi) {
    ull r;
    asm("mov.b64 %0, {%1, %2};" : "=l"(r) : "f"(lo), "f"(hi));
    return r;
}
__device__ __forceinline__ float2 unpack2(ull v) {
    float2 f;
    asm("mov.b64 {%0, %1}, %2;" : "=f"(f.x), "=f"(f.y) : "l"(v));
    return f;
}
__device__ __forceinline__ float sigmoidf_(float v) {
    return 1.f / (1.f + expf(-v));
}
__device__ __forceinline__ void cp_async16(void* smem, const void* g) {
    uint32_t s = (uint32_t)__cvta_generic_to_shared(smem);
    asm volatile("cp.async.cg.shared.global [%0], [%1], 16;" :: "r"(s), "l"(g));
}
__device__ __forceinline__ float to_tf32(float x) {
    uint32_t r;
    asm("cvt.rna.tf32.f32 %0, %1;" : "=r"(r) : "f"(x));
    return __uint_as_float(r);
}
__device__ __forceinline__ void mma_tf32(
    float& d0, float& d1, float& d2, float& d3,
    uint32_t a0, uint32_t a1, uint32_t a2, uint32_t a3,
    uint32_t b0, uint32_t b1)
{
    asm volatile(
        "mma.sync.aligned.m16n8k8.row.col.f32.tf32.tf32.f32 "
        "{%0,%1,%2,%3}, {%4,%5,%6,%7}, {%8,%9}, {%0,%1,%2,%3};"
        : "+f"(d0), "+f"(d1), "+f"(d2), "+f"(d3)
        : "r"(a0), "r"(a1), "r"(a2), "r"(a3), "r"(b0), "r"(b1));
}

// ---------------------------------------------------------------------------
// Kernel 0a: weight transform  reg_w[o][ic][kh][kw] -> g_wt[(g*9+k)*16+c][o]
// tf32-rounded for the MMA.
// ---------------------------------------------------------------------------
__global__ void wt_transform_kernel(const float* __restrict__ w, float* __restrict__ wt)
{
    int i = blockIdx.x * 256 + threadIdx.x;   // 36864 total
    int o = i & 63;
    int r = i >> 6;
    int c = r & 15;
    int r2 = r >> 4;
    int k = r2 % 9, g = r2 / 9;
    wt[i] = to_tf32(w[(o * 64 + g * 16 + c) * 9 + k]);
}

// ---------------------------------------------------------------------------
// Kernel 0b: NCHW -> group-split transpose: [b][64][HW] -> [b*4+g][HW][16]
// ---------------------------------------------------------------------------
__global__ __launch_bounds__(256) void gsplit_kernel(
    const float* __restrict__ in, float* __restrict__ outp)
{
    __shared__ float t[32][33];
    const int tx = threadIdx.x & 31, ty = threadIdx.x >> 5;
    const int p0 = blockIdx.x * 32;
    const int c0 = blockIdx.y * 32;
    const int b  = blockIdx.z;
#pragma unroll
    for (int j = 0; j < 4; j++) {
        int c = c0 + ty + j * 8;
        t[ty + j * 8][tx] = in[((size_t)(b * Cc + c)) * HW + p0 + tx];
    }
    __syncthreads();
#pragma unroll
    for (int j = 0; j < 4; j++) {
        int p = p0 + ty + j * 8;
        int c = c0 + tx;
        int g = c >> 4, ci = c & 15;
        outp[((size_t)(b * 4 + g) * HW + p) * 16 + ci] = t[tx][ty + j * 8];
    }
}

// ---------------------------------------------------------------------------
// Kernel 1: offset conv (R6 version)
// ---------------------------------------------------------------------------
__global__ __launch_bounds__(256) void offset_conv_kernel(
    const float* __restrict__ wr, const float* __restrict__ src,
    const float* __restrict__ ow, const float* __restrict__ ob,
    float* __restrict__ out_off)
{
    __shared__ float s_in[8 * 18 * 34];
    __shared__ float s_w[8 * 9 * 20];

    const int tid = threadIdx.x;
    const int tx = tid & 31, ty = tid >> 5;
    const int x0 = blockIdx.x * 32, y0 = blockIdx.y * 16;
    const int bz = blockIdx.z;
    const int g = bz & 3, b = bz >> 2;

    ull acc[2][9];
#pragma unroll
    for (int p = 0; p < 2; p++)
#pragma unroll
        for (int j = 0; j < 9; j++) acc[p][j] = 0ull;

#pragma unroll 1
    for (int chunk = 0; chunk < 4; chunk++) {
        const float* base = (chunk < 2 ? wr : src)
                          + ((size_t)(b * Cc + g * Cgc + (chunk & 1) * 8)) * HW;
        for (int i = tid; i < 4896; i += 256) {
            int c = i / 612, r = i % 612;
            int iy = r / 34, ix = r % 34;
            int gy = y0 - 1 + iy, gx = x0 - 1 + ix;
            float v = 0.f;
            if (gy >= 0 && gy < Hc && gx >= 0 && gx < Wc)
                v = base[(size_t)c * HW + gy * Wc + gx];
            s_in[i] = v;
        }
        for (int i = tid; i < 1440; i += 256) {
            int o = i % 20;
            int ck = i / 20;
            int k = ck % 9, c = ck / 9;
            s_w[i] = (o < 18) ? ow[(o * 32 + chunk * 8 + c) * 9 + k] : 0.f;
        }
        __syncthreads();

#pragma unroll 2
        for (int c = 0; c < 8; c++) {
#pragma unroll
            for (int t = 0; t < 9; t++) {
                const int kh = t / 3, kw = t % 3;
                const float* wrow = &s_w[(c * 9 + t) * 20];
                ulonglong2 l0 = *(const ulonglong2*)(wrow);
                ulonglong2 l1 = *(const ulonglong2*)(wrow + 4);
                ulonglong2 l2 = *(const ulonglong2*)(wrow + 8);
                ulonglong2 l3 = *(const ulonglong2*)(wrow + 12);
                ull w8 = *(const ull*)(wrow + 16);
#pragma unroll
                for (int p = 0; p < 2; p++) {
                    float v = s_in[c * 612 + (ty + p * 8 + kh) * 34 + tx + kw];
                    ull vv = pack2(v, v);
                    acc[p][0] = ffma2(vv, l0.x, acc[p][0]);
                    acc[p][1] = ffma2(vv, l0.y, acc[p][1]);
                    acc[p][2] = ffma2(vv, l1.x, acc[p][2]);
                    acc[p][3] = ffma2(vv, l1.y, acc[p][3]);
                    acc[p][4] = ffma2(vv, l2.x, acc[p][4]);
                    acc[p][5] = ffma2(vv, l2.y, acc[p][5]);
                    acc[p][6] = ffma2(vv, l3.x, acc[p][6]);
                    acc[p][7] = ffma2(vv, l3.y, acc[p][7]);
                    acc[p][8] = ffma2(vv, w8,  acc[p][8]);
                }
            }
        }
        __syncthreads();
    }

    const int x = x0 + tx;
#pragma unroll
    for (int p = 0; p < 2; p++) {
        int y = y0 + ty + p * 8;
#pragma unroll
        for (int j = 0; j < 9; j++) {
            float2 f = unpack2(acc[p][j]);
            int o0 = 2 * j, o1 = 2 * j + 1;
            float v0 = 100.f * sigmoidf_(f.x + ob[o0]) - 50.f;
            float v1 = 100.f * sigmoidf_(f.y + ob[o1]) - 50.f;
            out_off[((size_t)(b * 72 + g * 18 + o0) * Hc + y) * Wc + x] = v0;
            out_off[((size_t)(b * 72 + g * 18 + o1) * Hc + y) * Wc + x] = v1;
        }
    }
}

// ---------------------------------------------------------------------------
// Kernel 2: modulator conv (R6 version)
// ---------------------------------------------------------------------------
__global__ __launch_bounds__(256) void mod_conv_kernel(
    const float* __restrict__ wr,
    const float* __restrict__ mw, const float* __restrict__ mb,
    float* __restrict__ modout)
{
    __shared__ float s_in[8 * 10 * 34];
    __shared__ float s_w[8 * 9 * 2 * 20];

    const int tid = threadIdx.x;
    const int tx = tid & 31;
    const int q = tid >> 5;
    const int ty = q & 3;
    const int oh = q >> 2;
    const int x0 = blockIdx.x * 32, y0 = blockIdx.y * 8;
    const int b = blockIdx.z;

    ull acc[2][9];
#pragma unroll
    for (int p = 0; p < 2; p++)
#pragma unroll
        for (int j = 0; j < 9; j++) acc[p][j] = 0ull;

#pragma unroll 1
    for (int chunk = 0; chunk < 8; chunk++) {
        const float* base = wr + ((size_t)(b * Cc + chunk * 8)) * HW;
        for (int i = tid; i < 2720; i += 256) {
            int c = i / 340, r = i % 340;
            int iy = r / 34, ix = r % 34;
            int gy = y0 - 1 + iy, gx = x0 - 1 + ix;
            float v = 0.f;
            if (gy >= 0 && gy < Hc && gx >= 0 && gx < Wc)
                v = base[(size_t)c * HW + gy * Wc + gx];
            s_in[i] = v;
        }
        for (int i = tid; i < 2880; i += 256) {
            int o = i % 20;
            int rr = i / 20;
            int h = rr & 1;
            int ck = rr >> 1;
            int k = ck % 9, c = ck / 9;
            s_w[i] = (o < 18) ? mw[((h * 18 + o) * 64 + chunk * 8 + c) * 9 + k] : 0.f;
        }
        __syncthreads();

#pragma unroll 2
        for (int c = 0; c < 8; c++) {
#pragma unroll
            for (int t = 0; t < 9; t++) {
                const int kh = t / 3, kw = t % 3;
                const float* wrow = &s_w[((c * 9 + t) * 2 + oh) * 20];
                ulonglong2 l0 = *(const ulonglong2*)(wrow);
                ulonglong2 l1 = *(const ulonglong2*)(wrow + 4);
                ulonglong2 l2 = *(const ulonglong2*)(wrow + 8);
                ulonglong2 l3 = *(const ulonglong2*)(wrow + 12);
                ull w8 = *(const ull*)(wrow + 16);
#pragma unroll
                for (int p = 0; p < 2; p++) {
                    float v = s_in[c * 340 + (ty + p * 4 + kh) * 34 + tx + kw];
                    ull vv = pack2(v, v);
                    acc[p][0] = ffma2(vv, l0.x, acc[p][0]);
                    acc[p][1] = ffma2(vv, l0.y, acc[p][1]);
                    acc[p][2] = ffma2(vv, l1.x, acc[p][2]);
                    acc[p][3] = ffma2(vv, l1.y, acc[p][3]);
                    acc[p][4] = ffma2(vv, l2.x, acc[p][4]);
                    acc[p][5] = ffma2(vv, l2.y, acc[p][5]);
                    acc[p][6] = ffma2(vv, l3.x, acc[p][6]);
                    acc[p][7] = ffma2(vv, l3.y, acc[p][7]);
                    acc[p][8] = ffma2(vv, w8,  acc[p][8]);
                }
            }
        }
        __syncthreads();
    }

    const int x = x0 + tx;
#pragma unroll
    for (int p = 0; p < 2; p++) {
        int y = y0 + ty + p * 4;
#pragma unroll
        for (int j = 0; j < 9; j++) {
            float2 f = unpack2(acc[p][j]);
            int o0 = oh * 18 + 2 * j, o1 = o0 + 1;
            float v0 = 2.f * sigmoidf_(f.x + mb[o0]);
            float v1 = 2.f * sigmoidf_(f.y + mb[o1]);
            modout[((size_t)(b * 36 + o0) * Hc + y) * Wc + x] = v0;
            modout[((size_t)(b * 36 + o1) * Hc + y) * Wc + x] = v1;
        }
    }
}

// ---------------------------------------------------------------------------
// Kernel 3: FUSED deform — cooperative gather + tf32 MMA GEMM.
// Block = 256 px. Gather (proven in R7): 8 lanes/px, row-pair loads, shfl
// x-combine; stores tf32-rounded vals. GEMM: mma.sync.m16n8k8 tf32.
// Warp w: M-tile outs [16*(w>>1)), N-half 128*(w&1). 32 HMMA/warp/stage.
// ---------------------------------------------------------------------------
__global__ __launch_bounds__(256, 2) void deform_fused_kernel(
    const float* __restrict__ gsp,   // [b*4+g][HW][16]
    const float* __restrict__ off,   // [B,72,H,W]
    const float* __restrict__ mod,   // [B,36,H,W]
    const float* __restrict__ gwt,   // [36*16][64] tf32-rounded
    float* __restrict__ out_x)
{
    __shared__ float s_val[2][16 * VPAD];
    __shared__ float s_wk[2][16 * 64];

    const int tid = threadIdx.x;
    const int warp = tid >> 5, lane = tid & 31;
    const int sub = lane >> 3;          // px within 4-px step
    const int jj = lane & 7;            // lane within px octet
    const int half = jj >> 2, qq = jj & 3;
    const int blk = blockIdx.x;
    const int b = blk / (HW / 256);
    const int ploc0 = (blk % (HW / 256)) * 256;

    // MMA mapping
    const int wo = warp >> 1;           // M tile: outs 16*wo
    const int wn = warp & 1;            // N half: px 128*wn
    const int lr = lane >> 2;           // 0..7
    const int lc = lane & 3;            // 0..3
    const float fhalf = (float)half;

    auto gather = [&](int i) {
        const int buf = i & 1;
        const int g = i / 9, k = i % 9;
        const int kh = k / 3, kw = k % 3;
        const float* gplane = gsp + (size_t)(b * 4 + g) * HW * 16;
        const float* offy = off + (size_t)(b * 72 + g * 18 + 2 * k) * HW + ploc0;
        const float* offx = offy + (size_t)HW;
        const float* modp = mod + (size_t)(b * 36 + g * 9 + k) * HW + ploc0;
        float* sv = s_val[buf];

#pragma unroll 4
        for (int s = 0; s < 8; s++) {
            const int pl = warp * 32 + s * 4 + sub;
            const int p = ploc0 + pl;
            const int yy = p / Wc, xx = p % Wc;
            float oy = __ldg(&offy[pl]);
            float ox = __ldg(&offx[pl]);
            float m  = __ldg(&modp[pl]);

            float py = oy + (float)(kh + yy - 1);
            float pxf = ox + (float)(kw + xx - 1);
            float fy = floorf(py), fx = floorf(pxf);
            float ly = py - fy, lx = pxf - fx;
            int y0 = (int)fy, x0 = (int)fx;

            float vx0 = (x0 >= 0 && x0 < Wc) ? 1.f : 0.f;
            float vx1 = (x0 >= -1 && x0 <= Wc - 2) ? 1.f : 0.f;
            float vy0 = (y0 >= 0 && y0 < Hc) ? 1.f : 0.f;
            float vy1 = (y0 >= -1 && y0 <= Hc - 2) ? 1.f : 0.f;

            int rbx = min(max(x0, 0), Wc - 2);
            int cx0 = min(max(x0, 0), Wc - 1);
            int cx1 = min(max(x0 + 1, 0), Wc - 1);
            float s0 = (float)(cx0 - rbx);
            float s1 = (float)(cx1 - rbx);
            float wx0 = (1.f - lx) * vx0;
            float wx1 = lx * vx1;
            float hw = wx0 * (s0 == fhalf ? 1.f : 0.f) + wx1 * (s1 == fhalf ? 1.f : 0.f);

            int ry0 = min(max(y0, 0), Hc - 1);
            int ry1 = min(max(y0 + 1, 0), Hc - 1);
            float a0 = (1.f - ly) * vy0 * m * hw;
            float a1 = ly * vy1 * m * hw;

            const float4* r0p = (const float4*)(gplane + ((size_t)(ry0 * Wc + rbx)) * 16) + jj;
            const float4* r1p = (const float4*)(gplane + ((size_t)(ry1 * Wc + rbx)) * 16) + jj;
            float4 v0 = __ldg(r0p);
            float4 v1 = __ldg(r1p);

            float4 u;
            u.x = v0.x * a0 + v1.x * a1;
            u.y = v0.y * a0 + v1.y * a1;
            u.z = v0.z * a0 + v1.z * a1;
            u.w = v0.w * a0 + v1.w * a1;
            u.x += __shfl_xor_sync(0xFFFFFFFFu, u.x, 4);
            u.y += __shfl_xor_sync(0xFFFFFFFFu, u.y, 4);
            u.z += __shfl_xor_sync(0xFFFFFFFFu, u.z, 4);
            u.w += __shfl_xor_sync(0xFFFFFFFFu, u.w, 4);

            if (half == 0) {
                int cb = qq * 4;
                sv[(cb + 0) * VPAD + pl] = to_tf32(u.x);
                sv[(cb + 1) * VPAD + pl] = to_tf32(u.y);
                sv[(cb + 2) * VPAD + pl] = to_tf32(u.z);
                sv[(cb + 3) * VPAD + pl] = to_tf32(u.w);
            }
        }
    };

    auto stage_w = [&](int i) {
        int flat = tid * 4;
        int c = flat >> 6, o = flat & 63;
        cp_async16(&s_wk[i & 1][c * 64 + o], &gwt[(i * 16 + c) * 64 + o]);
        asm volatile("cp.async.commit_group;" ::: "memory");
    };

    float d[16][4];
#pragma unroll
    for (int nt = 0; nt < 16; nt++)
#pragma unroll
        for (int j = 0; j < 4; j++) d[nt][j] = 0.f;

    stage_w(0);
    gather(0);

#pragma unroll 1
    for (int i = 0; i < 36; i++) {
        asm volatile("cp.async.wait_group 0;" ::: "memory");
        __syncthreads();
        if (i < 35) { stage_w(i + 1); gather(i + 1); }

        const float* sv = s_val[i & 1];
        const float* wk = s_wk[i & 1];
#pragma unroll
        for (int kc = 0; kc < 2; kc++) {
            const int arow = wo * 16 + lr;
            const int ak = kc * 8 + lc;
            uint32_t a0 = __float_as_uint(wk[ak * 64 + arow]);
            uint32_t a1 = __float_as_uint(wk[ak * 64 + arow + 8]);
            uint32_t a2 = __float_as_uint(wk[(ak + 4) * 64 + arow]);
            uint32_t a3 = __float_as_uint(wk[(ak + 4) * 64 + arow + 8]);
#pragma unroll
            for (int nt = 0; nt < 16; nt++) {
                const int n = wn * 128 + nt * 8 + lr;
                const int bk = kc * 8 + lc;
                uint32_t b0 = __float_as_uint(sv[bk * VPAD + n]);
                uint32_t b1 = __float_as_uint(sv[(bk + 4) * VPAD + n]);
                mma_tf32(d[nt][0], d[nt][1], d[nt][2], d[nt][3],
                         a0, a1, a2, a3, b0, b1);
            }
        }
    }

    // Epilogue: D[row=o][col=px]; c0,c1 at (o, 2lc..2lc+1), c2,c3 at (o+8,..)
    const int o0 = wo * 16 + lr;
#pragma unroll
    for (int nt = 0; nt < 16; nt++) {
        const size_t p = (size_t)ploc0 + wn * 128 + nt * 8 + 2 * lc;
        *(float2*)&out_x[((size_t)(b * Cc + o0)) * HW + p]     = make_float2(d[nt][0], d[nt][1]);
        *(float2*)&out_x[((size_t)(b * Cc + o0 + 8)) * HW + p] = make_float2(d[nt][2], d[nt][3]);
    }
}

// ---------------------------------------------------------------------------
extern "C" void kernel_launch(void* const* d_in, const int* in_sizes, int n_in,
                              void* d_out, int out_size)
{
    const float* warp_ref = (const float*)d_in[0];
    const float* source   = (const float*)d_in[1];
    const float* offset_w = (const float*)d_in[2];
    const float* offset_b = (const float*)d_in[3];
    const float* mod_w    = (const float*)d_in[4];
    const float* mod_b    = (const float*)d_in[5];
    const float* reg_w    = (const float*)d_in[6];

    float* out_x   = (float*)d_out;             // [B,64,H,W]
    float* out_off = (float*)d_out + X_ELEMS;   // [B,72,H,W]

    float *mod_scratch, *wt_scratch, *gsp_scratch;
    cudaGetSymbolAddress((void**)&mod_scratch, g_modulator);
    cudaGetSymbolAddress((void**)&wt_scratch, g_wt);
    cudaGetSymbolAddress((void**)&gsp_scratch, g_gsplit);

    dim3 blk(256);
    wt_transform_kernel<<<144, blk>>>(reg_w, wt_scratch);
    gsplit_kernel<<<dim3(HW / 32, 2, Bc), blk>>>(warp_ref, gsp_scratch);
    offset_conv_kernel<<<dim3(6, 12, 8), blk>>>(warp_ref, source, offset_w, offset_b, out_off);
    mod_conv_kernel<<<dim3(6, 24, 2), blk>>>(warp_ref, mod_w, mod_b, mod_scratch);
    deform_fused_kernel<<<dim3(Nsz / 256), blk>>>(gsp_scratch, out_off, mod_scratch, wt_scratch, out_x);
}